// round 2
// baseline (speedup 1.0000x reference)
#include <cuda_runtime.h>
#include <cstdint>

#define B_  256
#define T_  512
#define I_  64
#define H_  512
#define R_TOTAL (B_*T_)      // 131072 rows of xh

#define CLUSTER 8
#define NGROUP  16           // 16 batch groups
#define BC      16           // batch rows per cluster
#define B_THREADS 128

#define A_ROWS 128
#define A_THREADS 256

// -------- scratch (static device globals; no allocation in kernel_launch) -----
__device__ float g_xh[(size_t)R_TOTAL * H_];          // 268 MB: x @ W_xh + b
__device__ float g_h[2][NGROUP][H_][BC];              // double-buffered h, [hid][row] transposed

// ---------------- helpers: packed f32x2 ----------------
__device__ __forceinline__ void ffma2(unsigned long long &d, unsigned long long a, unsigned long long b) {
    asm("fma.rn.f32x2 %0, %1, %2, %0;" : "+l"(d) : "l"(a), "l"(b));
}
__device__ __forceinline__ unsigned long long dup2(float w) {
    unsigned long long r;
    asm("mov.b64 %0, {%1, %1};" : "=l"(r) : "f"(w));
    return r;
}
__device__ __forceinline__ float2 unpack2(unsigned long long v) {
    float2 r;
    asm("mov.b64 {%0, %1}, %2;" : "=f"(r.x), "=f"(r.y) : "l"(v));
    return r;
}

// ================= Kernel A: xh = x @ W_xh + b =================
__global__ void __launch_bounds__(A_THREADS) kA(const float* __restrict__ x,
                                                const float* __restrict__ Wxh,
                                                const float* __restrict__ bias) {
    extern __shared__ float sm[];
    float* W_s = sm;                   // [64][512]
    float* x_s = sm + I_ * H_;         // [128][64]
    const int tid = threadIdx.x;
    const int m0 = blockIdx.x * A_ROWS;

    {   // load W_xh (32768 floats, contiguous)
        const float4* src = (const float4*)Wxh;
        float4* dst = (float4*)W_s;
        #pragma unroll
        for (int i = tid; i < I_ * H_ / 4; i += A_THREADS) dst[i] = src[i];
    }
    {   // load x tile (8192 floats, contiguous)
        const float4* src = (const float4*)(x + (size_t)m0 * I_);
        float4* dst = (float4*)x_s;
        #pragma unroll
        for (int i = tid; i < A_ROWS * I_ / 4; i += A_THREADS) dst[i] = src[i];
    }
    __syncthreads();

    const int j0 = tid, j1 = tid + 256;
    const float bj0 = bias[j0], bj1 = bias[j1];

    for (int blk = 0; blk < A_ROWS / 8; blk++) {
        float acc0[8], acc1[8];
        #pragma unroll
        for (int r = 0; r < 8; r++) { acc0[r] = 0.f; acc1[r] = 0.f; }
        #pragma unroll 4
        for (int k = 0; k < I_; k++) {
            float w0 = W_s[k * H_ + j0];
            float w1 = W_s[k * H_ + j1];
            #pragma unroll
            for (int r = 0; r < 8; r++) {
                float xv = x_s[(blk * 8 + r) * I_ + k];
                acc0[r] = fmaf(xv, w0, acc0[r]);
                acc1[r] = fmaf(xv, w1, acc1[r]);
            }
        }
        #pragma unroll
        for (int r = 0; r < 8; r++) {
            size_t row = (size_t)(m0 + blk * 8 + r);
            g_xh[row * H_ + j0] = acc0[r] + bj0;
            g_xh[row * H_ + j1] = acc1[r] + bj1;
        }
    }
}

// ================= Kernel B: recurrence =================
// Cluster of 8 CTAs owns 16 batch rows. CTA `rank` holds W_hh[:, rank*64 .. +64)
// in SMEM forever. Per step: stage full h (16x512) from L2 into SMEM, compute
// h_new[16,64] with packed f32x2 FFMA, tanh, publish slice to L2, cluster barrier.
__global__ void __launch_bounds__(B_THREADS) __cluster_dims__(CLUSTER, 1, 1)
kB(const float* __restrict__ Whh) {
    extern __shared__ float sm[];
    float* W_s = sm;                   // [512][64]
    float* h_s = sm + H_ * 64;         // [512][16]  (hid-major, row minor)
    const int tid  = threadIdx.x;
    const int rank = blockIdx.x % CLUSTER;
    const int bg   = blockIdx.x / CLUSTER;
    const int jbase = rank * 64;
    const int b0 = bg * BC;

    // load W_hh column slice: W_s[k][0..63] = Whh[k][jbase..jbase+63]
    for (int i = tid; i < H_ * 16; i += B_THREADS) {   // i over (k, quad-of-4)
        int k = i >> 4, q = i & 15;
        *(float4*)&W_s[k * 64 + q * 4] =
            *(const float4*)&Whh[(size_t)k * H_ + jbase + q * 4];
    }
    // zero our slice of h buffer 0: [jbase..jbase+64) x 16 rows = 256 float4
    for (int i = tid; i < 256; i += B_THREADS) {
        __stcg((float4*)&g_h[0][bg][jbase + (i >> 2)][(i & 3) * 4],
               make_float4(0.f, 0.f, 0.f, 0.f));
    }
    __threadfence();
    asm volatile("barrier.cluster.arrive.aligned;" ::: "memory");
    asm volatile("barrier.cluster.wait.aligned;" ::: "memory");

    const int cp = tid & 31;           // column pair index 0..31
    const int rg = tid >> 5;           // row group 0..3
    const int j0 = cp * 2;             // local col (even)
    const int r0 = rg * 4;             // first of 4 batch rows
    const uint32_t h_addr0 = (uint32_t)__cvta_generic_to_shared(h_s) + r0 * 4;

    for (int t = 0; t < T_; t++) {
        const int cur = t & 1, nxt = cur ^ 1;

        // stage h (8192 floats) from L2 (must bypass L1: peers wrote it)
        {
            const float4* src = (const float4*)&g_h[cur][bg][0][0];
            float4* dst = (float4*)h_s;
            #pragma unroll
            for (int i = 0; i < 2048 / B_THREADS; i++)
                dst[tid + i * B_THREADS] = __ldcg(&src[tid + i * B_THREADS]);
        }
        // prefetch xh for my 4 rows x 2 cols
        float2 xh[4];
        #pragma unroll
        for (int r = 0; r < 4; r++)
            xh[r] = *(const float2*)(g_xh +
                     ((size_t)(b0 + r0 + r) * T_ + t) * H_ + jbase + j0);
        __syncthreads();

        unsigned long long a00 = 0ull, a01 = 0ull, a10 = 0ull, a11 = 0ull;
        #pragma unroll 8
        for (int k = 0; k < H_; k++) {
            unsigned long long h01, h23;   // h[k][r0..r0+1], h[k][r0+2..r0+3]
            asm volatile("ld.shared.v2.b64 {%0,%1}, [%2];"
                         : "=l"(h01), "=l"(h23)
                         : "r"(h_addr0 + k * 64) : "memory");
            float2 wv = *(const float2*)&W_s[k * 64 + j0];
            unsigned long long w0 = dup2(wv.x), w1 = dup2(wv.y);
            ffma2(a00, h01, w0); ffma2(a01, h23, w0);
            ffma2(a10, h01, w1); ffma2(a11, h23, w1);
        }

        float2 c0l = unpack2(a00), c0h = unpack2(a01);
        float2 c1l = unpack2(a10), c1h = unpack2(a11);
        float4 out0, out1;
        out0.x = tanhf(c0l.x + xh[0].x);
        out0.y = tanhf(c0l.y + xh[1].x);
        out0.z = tanhf(c0h.x + xh[2].x);
        out0.w = tanhf(c0h.y + xh[3].x);
        out1.x = tanhf(c1l.x + xh[0].y);
        out1.y = tanhf(c1l.y + xh[1].y);
        out1.z = tanhf(c1h.x + xh[2].y);
        out1.w = tanhf(c1h.y + xh[3].y);
        __stcg((float4*)&g_h[nxt][bg][jbase + j0][r0], out0);
        __stcg((float4*)&g_h[nxt][bg][jbase + j0 + 1][r0], out1);

        __threadfence();
        asm volatile("barrier.cluster.arrive.aligned;" ::: "memory");
        asm volatile("barrier.cluster.wait.aligned;" ::: "memory");
    }
}

// ================= Kernel C: out = h_final @ fc_w^T + fc_b =================
__global__ void __launch_bounds__(256) kC(const float* __restrict__ fcw,
                                          const float* __restrict__ fcb,
                                          float* __restrict__ out) {
    const int b = threadIdx.x;         // 0..255
    const int bg = b >> 4, r = b & 15;
    float acc = 0.f;
    #pragma unroll 8
    for (int j = 0; j < H_; j++)
        acc = fmaf(g_h[0][bg][j][r], fcw[j], acc);   // final h lives in buffer 0
    out[b] = acc + fcb[0];
}

// ================= launch =================
extern "C" void kernel_launch(void* const* d_in, const int* in_sizes, int n_in,
                              void* d_out, int out_size) {
    const float* x    = (const float*)d_in[0];
    const float* Wxh  = (const float*)d_in[1];
    const float* Whh  = (const float*)d_in[2];
    const float* bias = (const float*)d_in[3];
    const float* fcw  = (const float*)d_in[4];
    const float* fcb  = (const float*)d_in[5];
    float* out = (float*)d_out;

    const int smemA = (I_ * H_ + A_ROWS * I_) * 4;      // 163840
    const int smemB = (H_ * 64 + H_ * BC) * 4;          // 163840
    cudaFuncSetAttribute(kA, cudaFuncAttributeMaxDynamicSharedMemorySize, smemA);
    cudaFuncSetAttribute(kB, cudaFuncAttributeMaxDynamicSharedMemorySize, smemB);

    kA<<<R_TOTAL / A_ROWS, A_THREADS, smemA>>>(x, Wxh, bias);
    kB<<<NGROUP * CLUSTER, B_THREADS, smemB>>>(Whh);
    kC<<<1, 256>>>(fcw, fcb, out);
}

// round 3
// speedup vs baseline: 1.1808x; 1.1808x over previous
#include <cuda_runtime.h>
#include <cstdint>

#define B_  256
#define T_  512
#define I_  64
#define H_  512
#define R_TOTAL (B_*T_)      // 131072 rows of xh

#define CLUSTER 8
#define NGROUP  16           // 16 batch groups
#define BC      16           // batch rows per cluster
#define B_THREADS 128

#define A_ROWS 128
#define A_THREADS 256

// -------- scratch (static device globals; no allocation in kernel_launch) -----
__device__ float g_xh[(size_t)R_TOTAL * H_];          // 268 MB: x @ W_xh + b
__device__ float g_final[NGROUP][H_][BC];             // final hidden state, [hid][row]

// ---------------- helpers ----------------
__device__ __forceinline__ void ffma2(unsigned long long &d, unsigned long long a, unsigned long long b) {
    asm("fma.rn.f32x2 %0, %1, %2, %0;" : "+l"(d) : "l"(a), "l"(b));
}
__device__ __forceinline__ unsigned long long dup2(float w) {
    unsigned long long r;
    asm("mov.b64 %0, {%1, %1};" : "=l"(r) : "f"(w));
    return r;
}
__device__ __forceinline__ float2 unpack2(unsigned long long v) {
    float2 r;
    asm("mov.b64 {%0, %1}, %2;" : "=f"(r.x), "=f"(r.y) : "l"(v));
    return r;
}
__device__ __forceinline__ float tanh_ap(float x) {
    float y;
    asm("tanh.approx.f32 %0, %1;" : "=f"(y) : "f"(x));
    return y;
}

// ================= Kernel A: xh = x @ W_xh + b =================
__global__ void __launch_bounds__(A_THREADS) kA(const float* __restrict__ x,
                                                const float* __restrict__ Wxh,
                                                const float* __restrict__ bias) {
    extern __shared__ float sm[];
    float* W_s = sm;                   // [64][512]
    float* x_s = sm + I_ * H_;         // [128][64]
    const int tid = threadIdx.x;
    const int m0 = blockIdx.x * A_ROWS;

    {
        const float4* src = (const float4*)Wxh;
        float4* dst = (float4*)W_s;
        #pragma unroll
        for (int i = tid; i < I_ * H_ / 4; i += A_THREADS) dst[i] = src[i];
    }
    {
        const float4* src = (const float4*)(x + (size_t)m0 * I_);
        float4* dst = (float4*)x_s;
        #pragma unroll
        for (int i = tid; i < A_ROWS * I_ / 4; i += A_THREADS) dst[i] = src[i];
    }
    __syncthreads();

    const int j0 = tid, j1 = tid + 256;
    const float bj0 = bias[j0], bj1 = bias[j1];

    for (int blk = 0; blk < A_ROWS / 8; blk++) {
        float acc0[8], acc1[8];
        #pragma unroll
        for (int r = 0; r < 8; r++) { acc0[r] = 0.f; acc1[r] = 0.f; }
        #pragma unroll 4
        for (int k = 0; k < I_; k++) {
            float w0 = W_s[k * H_ + j0];
            float w1 = W_s[k * H_ + j1];
            #pragma unroll
            for (int r = 0; r < 8; r++) {
                float xv = x_s[(blk * 8 + r) * I_ + k];
                acc0[r] = fmaf(xv, w0, acc0[r]);
                acc1[r] = fmaf(xv, w1, acc1[r]);
            }
        }
        #pragma unroll
        for (int r = 0; r < 8; r++) {
            size_t row = (size_t)(m0 + blk * 8 + r);
            g_xh[row * H_ + j0] = acc0[r] + bj0;
            g_xh[row * H_ + j1] = acc1[r] + bj1;
        }
    }
}

// ================= Kernel B: recurrence (DSMEM exchange) =================
// Cluster of 8 CTAs owns 16 batch rows. CTA `rank` holds W_hh[:, rank*64..+64)
// in SMEM. Per step: compute h_new[16,64] from its own full SMEM copy of h,
// tanh.approx, push the slice into ALL 8 cluster CTAs' h SMEM (double-buffered)
// via st.shared::cluster, then one cluster barrier (release/acquire).
__global__ void __launch_bounds__(B_THREADS) __cluster_dims__(CLUSTER, 1, 1)
kB(const float* __restrict__ Whh) {
    extern __shared__ float sm[];
    float* W_s = sm;                   // [512][64]  128 KB
    float* h_s = sm + H_ * 64;         // [2][512][16] 64 KB, hid-major, row minor
    const int tid  = threadIdx.x;
    const int rank = blockIdx.x % CLUSTER;   // == cluster_ctarank
    const int bg   = blockIdx.x / CLUSTER;
    const int jbase = rank * 64;
    const int b0 = bg * BC;

    // load W_hh column slice: W_s[k][0..63] = Whh[k][jbase..jbase+63]
    for (int i = tid; i < H_ * 16; i += B_THREADS) {
        int k = i >> 4, q = i & 15;
        *(float4*)&W_s[k * 64 + q * 4] =
            *(const float4*)&Whh[(size_t)k * H_ + jbase + q * 4];
    }
    // zero own h buffer 0 (512*16 floats = 2048 float4)
    for (int i = tid; i < H_ * 16 / 4; i += B_THREADS)
        ((float4*)h_s)[i] = make_float4(0.f, 0.f, 0.f, 0.f);
    __syncthreads();

    // tiling: warp = (rowgroup rg in {0,1}) x (colgroup cg in {0,1})
    // thread: 1 column (jloc), 8 batch rows (r0..r0+7)
    const int warp = tid >> 5, lane = tid & 31;
    const int rg = warp & 1, cg = warp >> 1;
    const int jloc  = cg * 32 + lane;
    const int jglob = jbase + jloc;
    const int r0 = rg * 8;

    // remote (and self) store base addresses, hoisted out of the t-loop
    uint32_t local_base = (uint32_t)__cvta_generic_to_shared(h_s)
                        + (uint32_t)((jglob * 16 + r0) * 4);
    uint32_t peer_base[CLUSTER];
    #pragma unroll
    for (int c = 0; c < CLUSTER; c++)
        asm("mapa.shared::cluster.u32 %0, %1, %2;"
            : "=r"(peer_base[c]) : "r"(local_base), "r"(c));
    const uint32_t BUFB = H_ * 16 * 4;   // 32 KB per h buffer

    for (int t = 0; t < T_; t++) {
        const float* hb = h_s + (t & 1) * (H_ * 16);

        // prefetch xh for my 8 rows (coalesced 128B per warp per row)
        float xh[8];
        #pragma unroll
        for (int r = 0; r < 8; r++)
            xh[r] = g_xh[((size_t)(b0 + r0 + r) * T_ + t) * H_ + jglob];

        unsigned long long a0 = 0ull, a1 = 0ull, a2 = 0ull, a3 = 0ull;
        #pragma unroll 8
        for (int k = 0; k < H_; k++) {
            unsigned long long wd = dup2(W_s[k * 64 + jloc]);     // 128B/warp, 1 wf
            ulonglong2 hA = *(const ulonglong2*)&hb[k * 16 + r0];       // 16B bcast
            ulonglong2 hB = *(const ulonglong2*)&hb[k * 16 + r0 + 4];   // 16B bcast
            ffma2(a0, hA.x, wd); ffma2(a1, hA.y, wd);
            ffma2(a2, hB.x, wd); ffma2(a3, hB.y, wd);
        }

        float2 c0 = unpack2(a0), c1 = unpack2(a1);
        float2 c2 = unpack2(a2), c3 = unpack2(a3);
        float o0 = tanh_ap(c0.x + xh[0]);
        float o1 = tanh_ap(c0.y + xh[1]);
        float o2 = tanh_ap(c1.x + xh[2]);
        float o3 = tanh_ap(c1.y + xh[3]);
        float o4 = tanh_ap(c2.x + xh[4]);
        float o5 = tanh_ap(c2.y + xh[5]);
        float o6 = tanh_ap(c3.x + xh[6]);
        float o7 = tanh_ap(c3.y + xh[7]);

        // push my 8 results (col jglob, rows r0..r0+7) into every cluster CTA's
        // next h buffer
        const uint32_t woff = ((t + 1) & 1) * BUFB;
        #pragma unroll
        for (int c = 0; c < CLUSTER; c++) {
            asm volatile("st.shared::cluster.v4.f32 [%0], {%1,%2,%3,%4};"
                         :: "r"(peer_base[c] + woff),
                            "f"(o0), "f"(o1), "f"(o2), "f"(o3) : "memory");
            asm volatile("st.shared::cluster.v4.f32 [%0], {%1,%2,%3,%4};"
                         :: "r"(peer_base[c] + woff + 16),
                            "f"(o4), "f"(o5), "f"(o6), "f"(o7) : "memory");
        }

        if (t == T_ - 1) {
            __stcg((float4*)&g_final[bg][jglob][r0],     make_float4(o0, o1, o2, o3));
            __stcg((float4*)&g_final[bg][jglob][r0 + 4], make_float4(o4, o5, o6, o7));
        }

        // release my DSMEM stores / acquire peers' stores
        asm volatile("barrier.cluster.arrive.aligned;" ::: "memory");
        asm volatile("barrier.cluster.wait.aligned;" ::: "memory");
    }
}

// ================= Kernel C: out = h_final @ fc_w^T + fc_b =================
__global__ void __launch_bounds__(256) kC(const float* __restrict__ fcw,
                                          const float* __restrict__ fcb,
                                          float* __restrict__ out) {
    const int b = threadIdx.x;         // 0..255
    const int bg = b >> 4, r = b & 15;
    float acc = 0.f;
    #pragma unroll 8
    for (int j = 0; j < H_; j++)
        acc = fmaf(g_final[bg][j][r], fcw[j], acc);
    out[b] = acc + fcb[0];
}

// ================= launch =================
extern "C" void kernel_launch(void* const* d_in, const int* in_sizes, int n_in,
                              void* d_out, int out_size) {
    const float* x    = (const float*)d_in[0];
    const float* Wxh  = (const float*)d_in[1];
    const float* Whh  = (const float*)d_in[2];
    const float* bias = (const float*)d_in[3];
    const float* fcw  = (const float*)d_in[4];
    const float* fcb  = (const float*)d_in[5];
    float* out = (float*)d_out;

    const int smemA = (I_ * H_ + A_ROWS * I_) * 4;            // 163840
    const int smemB = (H_ * 64 + 2 * H_ * BC) * 4;            // 196608
    cudaFuncSetAttribute(kA, cudaFuncAttributeMaxDynamicSharedMemorySize, smemA);
    cudaFuncSetAttribute(kB, cudaFuncAttributeMaxDynamicSharedMemorySize, smemB);

    kA<<<R_TOTAL / A_ROWS, A_THREADS, smemA>>>(x, Wxh, bias);
    kB<<<NGROUP * CLUSTER, B_THREADS, smemB>>>(Whh);
    kC<<<1, 256>>>(fcw, fcb, out);
}